// round 2
// baseline (speedup 1.0000x reference)
#include <cuda_runtime.h>
#include <cuda_bf16.h>
#include <math.h>
#include <stdint.h>

// Problem constants
#define Bdim 64
#define Ldim 80
#define KDET 36
#define DV   256
#define DQ   512
#define Hdim 512
#define NLB  (Ldim*Bdim)   // 5120

// Scratch (__device__ globals: no runtime allocation allowed)
__device__ float          g_sumsq[3];          // ||Vv||^2, ||Vq||^2, ||Vl||^2
__device__ __nv_bfloat16  g_Wv[Hdim*DV];       // Vv in bf16 (unscaled)
__device__ __nv_bfloat16  g_Wq[Hdim*DQ];       // Vq in bf16 (unscaled)
__device__ float          g_u[(size_t)NLB*Hdim]; // u[lb][h] = relu(s_q*(ctx.Vq_h)+bq_h)*s_l*Vl_h

// ---------------------------------------------------------------------------
__global__ void k_zero() { if (threadIdx.x < 3) g_sumsq[threadIdx.x] = 0.f; }

__global__ void k_sumsq(const float* __restrict__ Vv, const float* __restrict__ Vq,
                        const float* __restrict__ Vl) {
    float sv = 0.f, sq = 0.f, sl = 0.f;
    int stride = gridDim.x * blockDim.x;
    for (int i = blockIdx.x * blockDim.x + threadIdx.x; i < Hdim*DQ; i += stride) {
        float x = Vq[i]; sq += x*x;
        if (i < Hdim*DV) { float y = Vv[i]; sv += y*y; }
        if (i < Hdim)    { float z = Vl[i]; sl += z*z; }
    }
    #pragma unroll
    for (int o = 16; o; o >>= 1) {
        sv += __shfl_xor_sync(~0u, sv, o);
        sq += __shfl_xor_sync(~0u, sq, o);
        sl += __shfl_xor_sync(~0u, sl, o);
    }
    __shared__ float rs[3][8];
    int w = threadIdx.x >> 5;
    if ((threadIdx.x & 31) == 0) { rs[0][w] = sv; rs[1][w] = sq; rs[2][w] = sl; }
    __syncthreads();
    if (threadIdx.x == 0) {
        float a = 0.f, b = 0.f, c = 0.f;
        for (int i = 0; i < 8; ++i) { a += rs[0][i]; b += rs[1][i]; c += rs[2][i]; }
        atomicAdd(&g_sumsq[0], a); atomicAdd(&g_sumsq[1], b); atomicAdd(&g_sumsq[2], c);
    }
}

__global__ void k_convert(const float* __restrict__ Vv, const float* __restrict__ Vq) {
    int i = blockIdx.x * blockDim.x + threadIdx.x;
    if (i < Hdim*DQ) g_Wq[i] = __float2bfloat16(Vq[i]);
    if (i < Hdim*DV) g_Wv[i] = __float2bfloat16(Vv[i]);
}

// ---------------------------------------------------------------------------
// warp mma m16n8k16 bf16 (A row-major in smem, B col-major == [h][d] rows in smem)
__device__ __forceinline__ void mma_bf16(float* c, const unsigned* a, const unsigned* b) {
    asm volatile(
        "mma.sync.aligned.m16n8k16.row.col.f32.bf16.bf16.f32 "
        "{%0,%1,%2,%3}, {%4,%5,%6,%7}, {%8,%9}, {%0,%1,%2,%3};\n"
        : "+f"(c[0]), "+f"(c[1]), "+f"(c[2]), "+f"(c[3])
        : "r"(a[0]), "r"(a[1]), "r"(a[2]), "r"(a[3]), "r"(b[0]), "r"(b[1]));
}

// ---------------------------------------------------------------------------
// k_u: u[lb][h] for one l per block (64 b-rows), GEMM [64 x 512] x [512 x 512]^T
#define SA_U 520   // bf16 elems per row (512 + 8 pad -> conflict-free frag loads)
__global__ __launch_bounds__(256, 1)
void k_u(const float* __restrict__ ctx, const float* __restrict__ gq,
         const float* __restrict__ bq, const float* __restrict__ Vl,
         const float* __restrict__ gl) {
    extern __shared__ char sm[];
    __nv_bfloat16* A    = (__nv_bfloat16*)sm;                 // 64 x 520 bf16  (66560 B)
    __nv_bfloat16* W    = (__nv_bfloat16*)(sm + 66560);       // 64 x 520 bf16  (66560 B)
    float*         bq_s = (float*)(sm + 133120);              // 512 f32
    float*         wl_s = (float*)(sm + 135168);              // 512 f32

    const int tid = threadIdx.x;
    const int l   = blockIdx.x;
    const float s_q = gq[0] * rsqrtf(g_sumsq[1]);
    const float s_l = gl[0] * rsqrtf(g_sumsq[2]);

    for (int i = tid; i < Hdim; i += 256) { bq_s[i] = bq[i]; wl_s[i] = s_l * Vl[i]; }

    // stage ctx rows b=0..63 (strided in gmem), convert to bf16
    #pragma unroll 4
    for (int it = 0; it < 32; ++it) {
        int i  = tid + it * 256;          // 8192 float4 total
        int r  = i >> 7, c4 = i & 127;
        float4 f = *(const float4*)(ctx + ((size_t)r * Ldim + l) * DQ + c4 * 4);
        __nv_bfloat16* ap = A + r * SA_U + c4 * 4;
        *(__nv_bfloat162*)(ap)     = __floats2bfloat162_rn(f.x, f.y);
        *(__nv_bfloat162*)(ap + 2) = __floats2bfloat162_rn(f.z, f.w);
    }

    const int warp = tid >> 5, lane = tid & 31;
    const int wm = warp & 1, wn = warp >> 1;      // 2 warps over M(64), 4 over N(64)
    const int grp = lane >> 2, lane4 = lane & 3;

    for (int chunk = 0; chunk < 8; ++chunk) {
        __syncthreads();
        const int h0c = chunk * 64;
        #pragma unroll 4
        for (int it = 0; it < 16; ++it) {
            int i = tid + it * 256;       // 4096 uint4 (64 rows x 64)
            int r = i >> 6, c8 = i & 63;
            *(uint4*)(W + r * SA_U + c8 * 8) =
                *(const uint4*)(g_Wq + (size_t)(h0c + r) * DQ + c8 * 8);
        }
        __syncthreads();

        float acc[2][2][4] = {};
        #pragma unroll
        for (int ks = 0; ks < 32; ++ks) {
            const int k0 = ks * 16;
            unsigned a[2][4], b[2][2];
            #pragma unroll
            for (int mf = 0; mf < 2; ++mf) {
                const __nv_bfloat16* p = A + (wm*32 + mf*16 + grp) * SA_U + k0 + lane4*2;
                a[mf][0] = *(const unsigned*)(p);
                a[mf][1] = *(const unsigned*)(p + 8*SA_U);
                a[mf][2] = *(const unsigned*)(p + 8);
                a[mf][3] = *(const unsigned*)(p + 8*SA_U + 8);
            }
            #pragma unroll
            for (int nf = 0; nf < 2; ++nf) {
                const __nv_bfloat16* p = W + (wn*16 + nf*8 + grp) * SA_U + k0 + lane4*2;
                b[nf][0] = *(const unsigned*)(p);
                b[nf][1] = *(const unsigned*)(p + 8);
            }
            #pragma unroll
            for (int mf = 0; mf < 2; ++mf)
                #pragma unroll
                for (int nf = 0; nf < 2; ++nf)
                    mma_bf16(acc[mf][nf], a[mf], b[nf]);
        }

        // epilogue: u = relu(s_q*c + bq)*wl  -> gmem
        #pragma unroll
        for (int mf = 0; mf < 2; ++mf) {
            int r0 = wm*32 + mf*16 + grp;
            #pragma unroll
            for (int nf = 0; nf < 2; ++nf) {
                int h = h0c + wn*16 + nf*8 + lane4*2;
                float* up0 = &g_u[(size_t)(l*64 + r0)     * Hdim + h];
                float* up1 = &g_u[(size_t)(l*64 + r0 + 8) * Hdim + h];
                up0[0] = fmaxf(fmaf(s_q, acc[mf][nf][0], bq_s[h]),   0.f) * wl_s[h];
                up0[1] = fmaxf(fmaf(s_q, acc[mf][nf][1], bq_s[h+1]), 0.f) * wl_s[h+1];
                up1[0] = fmaxf(fmaf(s_q, acc[mf][nf][2], bq_s[h]),   0.f) * wl_s[h];
                up1[1] = fmaxf(fmaf(s_q, acc[mf][nf][3], bq_s[h+1]), 0.f) * wl_s[h+1];
            }
        }
    }
}

// ---------------------------------------------------------------------------
// k_main: per block, 2 (l,b) pairs. Fused: v-proj GEMM (bf16 MMA) -> logits ->
// softmax over k -> fp32 weighted sum of v (v read from gmem exactly once).
#define SA_M 264   // bf16 elems per row (256 + 8 pad)
__global__ __launch_bounds__(256, 1)
void k_main(const float* __restrict__ v, const int* __restrict__ lengths,
            const float* __restrict__ gv, const float* __restrict__ bv,
            float* __restrict__ out) {
    extern __shared__ char sm[];
    float*         vf   = (float*)sm;                      // [2][36][256] f32   (73728 B)
    __nv_bfloat16* A    = (__nv_bfloat16*)(sm + 73728);    // 96 x 264 bf16      (50688 B)
    __nv_bfloat16* W    = (__nv_bfloat16*)(sm + 124416);   // 64 x 264 bf16      (33792 B)
    float*         u_s  = (float*)(sm + 158208);           // 2 x 512 f32
    float*         bv_s = (float*)(sm + 162304);           // 512 f32
    float*         lg   = (float*)(sm + 164352);           // 96 f32 (logits -> weights)
    int*           len_s= (int*)(sm + 164736);             // 2

    const int tid = threadIdx.x;
    const int lb0 = blockIdx.x * 2;
    const float s_v = gv[0] * rsqrtf(g_sumsq[0]);

    // phase 0: zero A (pad rows must be 0), zero logits, stage u + bv
    for (int i = tid; i < (96 * SA_M * 2) / 4; i += 256) ((unsigned*)A)[i] = 0u;
    if (tid < 96)  lg[tid] = 0.f;
    if (tid < 256) ((float4*)u_s)[tid] = ((const float4*)(g_u + (size_t)lb0 * Hdim))[tid];
    if (tid < 128) ((float4*)bv_s)[tid] = ((const float4*)bv)[tid];
    __syncthreads();

    // phase 1: v -> fp32 smem + bf16 A tile (single gmem pass over v)
    const float* vsrc = v + (size_t)lb0 * KDET * DV;
    #pragma unroll 2
    for (int it = 0; it < 18; ++it) {
        int i   = tid + it * 256;         // 4608 float4
        int lbi = i / 2304;
        int j   = i - lbi * 2304;
        int k   = j >> 6, c4 = j & 63;
        float4 f = *(const float4*)(vsrc + (size_t)i * 4);
        *(float4*)(vf + (size_t)i * 4) = f;
        __nv_bfloat16* ap = A + (lbi*48 + k) * SA_M + c4 * 4;
        *(__nv_bfloat162*)(ap)     = __floats2bfloat162_rn(f.x, f.y);
        *(__nv_bfloat162*)(ap + 2) = __floats2bfloat162_rn(f.z, f.w);
    }

    const int warp = tid >> 5, lane = tid & 31;
    const int wm = warp & 1, wn = warp >> 1;      // 2 warps over M(96), 4 over N(64)
    const int grp = lane >> 2, lane4 = lane & 3;

    for (int chunk = 0; chunk < 8; ++chunk) {
        __syncthreads();
        const int h0c = chunk * 64;
        #pragma unroll 4
        for (int it = 0; it < 8; ++it) {
            int i = tid + it * 256;       // 2048 uint4 (64 rows x 32)
            int r = i >> 5, c8 = i & 31;
            *(uint4*)(W + r * SA_M + c8 * 8) =
                *(const uint4*)(g_Wv + (size_t)(h0c + r) * DV + c8 * 8);
        }
        __syncthreads();

        float acc[3][2][4] = {};
        #pragma unroll
        for (int ks = 0; ks < 16; ++ks) {
            const int k0 = ks * 16;
            unsigned a[3][4], b[2][2];
            #pragma unroll
            for (int mf = 0; mf < 3; ++mf) {
                const __nv_bfloat16* p = A + (wm*48 + mf*16 + grp) * SA_M + k0 + lane4*2;
                a[mf][0] = *(const unsigned*)(p);
                a[mf][1] = *(const unsigned*)(p + 8*SA_M);
                a[mf][2] = *(const unsigned*)(p + 8);
                a[mf][3] = *(const unsigned*)(p + 8*SA_M + 8);
            }
            #pragma unroll
            for (int nf = 0; nf < 2; ++nf) {
                const __nv_bfloat16* p = W + (wn*16 + nf*8 + grp) * SA_M + k0 + lane4*2;
                b[nf][0] = *(const unsigned*)(p);
                b[nf][1] = *(const unsigned*)(p + 8);
            }
            #pragma unroll
            for (int mf = 0; mf < 3; ++mf)
                #pragma unroll
                for (int nf = 0; nf < 2; ++nf)
                    mma_bf16(acc[mf][nf], a[mf], b[nf]);
        }

        // epilogue: logit partial = sum_h relu(s_v*c + bv)*u ; reduce over lane%4, atomic to smem
        #pragma unroll
        for (int mf = 0; mf < 3; ++mf) {
            int r0 = wm*48 + mf*16 + grp;      // row (lb index = wm by construction)
            float slo = 0.f, shi = 0.f;
            #pragma unroll
            for (int nf = 0; nf < 2; ++nf) {
                int h = h0c + wn*16 + nf*8 + lane4*2;
                float u0 = u_s[wm*Hdim + h], u1 = u_s[wm*Hdim + h + 1];
                float b0 = bv_s[h], b1 = bv_s[h+1];
                slo += fmaxf(fmaf(s_v, acc[mf][nf][0], b0), 0.f) * u0
                     + fmaxf(fmaf(s_v, acc[mf][nf][1], b1), 0.f) * u1;
                shi += fmaxf(fmaf(s_v, acc[mf][nf][2], b0), 0.f) * u0
                     + fmaxf(fmaf(s_v, acc[mf][nf][3], b1), 0.f) * u1;
            }
            slo += __shfl_xor_sync(~0u, slo, 1); slo += __shfl_xor_sync(~0u, slo, 2);
            shi += __shfl_xor_sync(~0u, shi, 1); shi += __shfl_xor_sync(~0u, shi, 2);
            if (lane4 == 0) { atomicAdd(&lg[r0], slo); atomicAdd(&lg[r0 + 8], shi); }
        }
    }
    __syncthreads();

    // softmax over valid k (serial per lb — only 36 entries)
    const int lbi = tid >> 7, t = tid & 127;
    if (t == 0) {
        int len = lengths[lb0 + lbi];
        if (len > KDET) len = KDET;
        len_s[lbi] = len;
        if (len > 0) {
            float m = -1e30f;
            for (int k = 0; k < len; ++k) m = fmaxf(m, lg[lbi*48 + k]);
            float s = 0.f;
            for (int k = 0; k < len; ++k) { float e = __expf(lg[lbi*48 + k] - m); lg[lbi*48 + k] = e; s += e; }
            float inv = 1.f / s;
            for (int k = 0; k < len; ++k) lg[lbi*48 + k] *= inv;
        }
    }
    __syncthreads();

    // fp32 weighted sum of v (from smem), write out [B, L, Dv]
    const int len = len_s[lbi];
    const int d0  = t * 2;
    float ax = 0.f, ay = 0.f;
    const float* vr = vf + lbi * (KDET * DV) + d0;
    for (int k = 0; k < len; ++k) {
        float w  = lg[lbi*48 + k];
        float2 vv = *(const float2*)(vr + k * DV);
        ax = fmaf(w, vv.x, ax);
        ay = fmaf(w, vv.y, ay);
    }
    const int lb = lb0 + lbi, l = lb >> 6, bb = lb & 63;
    float2 o; o.x = ax; o.y = ay;
    *(float2*)(out + ((size_t)bb * Ldim + l) * DV + d0) = o;
}

// ---------------------------------------------------------------------------
extern "C" void kernel_launch(void* const* d_in, const int* in_sizes, int n_in,
                              void* d_out, int out_size) {
    const float* ctx     = (const float*)d_in[0];
    const float* v       = (const float*)d_in[1];
    const int*   lengths = (const int*)  d_in[2];
    const float* Vv      = (const float*)d_in[3];
    const float* gv      = (const float*)d_in[4];
    const float* bvp     = (const float*)d_in[5];
    const float* Vq      = (const float*)d_in[6];
    const float* gq      = (const float*)d_in[7];
    const float* bq      = (const float*)d_in[8];
    const float* Vl      = (const float*)d_in[9];
    const float* gl      = (const float*)d_in[10];
    // d_in[11] = bl: constant shift on logits -> cancels in softmax, unused.
    (void)in_sizes; (void)n_in; (void)out_size;

    cudaFuncSetAttribute(k_u,    cudaFuncAttributeMaxDynamicSharedMemorySize, 137216);
    cudaFuncSetAttribute(k_main, cudaFuncAttributeMaxDynamicSharedMemorySize, 164768);

    k_zero<<<1, 32>>>();
    k_sumsq<<<128, 256>>>(Vv, Vq, Vl);
    k_convert<<<(Hdim*DQ + 255) / 256, 256>>>(Vv, Vq);
    k_u<<<Ldim, 256, 137216>>>(ctx, gq, bq, Vl, gl);
    k_main<<<NLB / 2, 256, 164768>>>(v, lengths, gv, bvp, (float*)d_out);
}

// round 5
// speedup vs baseline: 1.7861x; 1.7861x over previous
#include <cuda_runtime.h>
#include <cuda_bf16.h>
#include <math.h>
#include <stdint.h>

// Problem constants
#define Bdim 64
#define Ldim 80
#define KDET 36
#define DV   256
#define DQ   512
#define Hdim 512
#define NLB  (Ldim*Bdim)   // 5120

// Scratch (__device__ globals: no runtime allocation allowed)
__device__ float          g_sumsq[3];
__device__ __nv_bfloat16  g_Wv[Hdim*DV];
__device__ __nv_bfloat16  g_Wq[Hdim*DQ];
__device__ float          g_u[(size_t)NLB*Hdim];

// ---------------------------------------------------------------------------
__device__ __forceinline__ unsigned sptr(const void* p) {
    return (unsigned)__cvta_generic_to_shared(p);
}
__device__ __forceinline__ void ldsm4(unsigned* r, unsigned a) {
    asm volatile("ldmatrix.sync.aligned.m8n8.x4.shared.b16 {%0,%1,%2,%3}, [%4];\n"
                 : "=r"(r[0]), "=r"(r[1]), "=r"(r[2]), "=r"(r[3]) : "r"(a));
}
#define CPA16(dst, src) asm volatile("cp.async.cg.shared.global [%0], [%1], 16;\n" :: "r"(dst), "l"(src))
#define CPCOMMIT()      asm volatile("cp.async.commit_group;\n")
#define CPWAIT1()       asm volatile("cp.async.wait_group 1;\n")
#define CPWAIT0()       asm volatile("cp.async.wait_group 0;\n")

__device__ __forceinline__ void mma_bf16(float* c, const unsigned* a, const unsigned* b) {
    asm volatile(
        "mma.sync.aligned.m16n8k16.row.col.f32.bf16.bf16.f32 "
        "{%0,%1,%2,%3}, {%4,%5,%6,%7}, {%8,%9}, {%0,%1,%2,%3};\n"
        : "+f"(c[0]), "+f"(c[1]), "+f"(c[2]), "+f"(c[3])
        : "r"(a[0]), "r"(a[1]), "r"(a[2]), "r"(a[3]), "r"(b[0]), "r"(b[1]));
}

// ---------------------------------------------------------------------------
__global__ void k_zero() { if (threadIdx.x < 3) g_sumsq[threadIdx.x] = 0.f; }

__global__ void k_sumsq(const float* __restrict__ Vv, const float* __restrict__ Vq,
                        const float* __restrict__ Vl) {
    float sv = 0.f, sq = 0.f, sl = 0.f;
    int stride = gridDim.x * blockDim.x;
    for (int i = blockIdx.x * blockDim.x + threadIdx.x; i < Hdim*DQ; i += stride) {
        float x = Vq[i]; sq += x*x;
        if (i < Hdim*DV) { float y = Vv[i]; sv += y*y; }
        if (i < Hdim)    { float z = Vl[i]; sl += z*z; }
    }
    #pragma unroll
    for (int o = 16; o; o >>= 1) {
        sv += __shfl_xor_sync(~0u, sv, o);
        sq += __shfl_xor_sync(~0u, sq, o);
        sl += __shfl_xor_sync(~0u, sl, o);
    }
    __shared__ float rs[3][8];
    int w = threadIdx.x >> 5;
    if ((threadIdx.x & 31) == 0) { rs[0][w] = sv; rs[1][w] = sq; rs[2][w] = sl; }
    __syncthreads();
    if (threadIdx.x == 0) {
        float a = 0.f, b = 0.f, c = 0.f;
        for (int i = 0; i < 8; ++i) { a += rs[0][i]; b += rs[1][i]; c += rs[2][i]; }
        atomicAdd(&g_sumsq[0], a); atomicAdd(&g_sumsq[1], b); atomicAdd(&g_sumsq[2], c);
    }
}

__global__ void k_convert(const float* __restrict__ Vv, const float* __restrict__ Vq) {
    int i = blockIdx.x * blockDim.x + threadIdx.x;
    if (i < Hdim*DQ) g_Wq[i] = __float2bfloat16(Vq[i]);
    if (i < Hdim*DV) g_Wv[i] = __float2bfloat16(Vv[i]);
}

// ---------------------------------------------------------------------------
// k_u: u[lb][h] = relu(s_q*(ctx.Vq_h)+bq_h)*s_l*Vl_h
// grid (80 l, 4 h-slices of 128). GEMM [64 x 512] x [512 x 128]^T per block,
// 2 chunks of 64 h-rows, SINGLE W buffer (137216 B total smem — proven config).
#define SU 520   // bf16 row stride (512 + 8 pad); ldsm conflict-free
__global__ __launch_bounds__(256, 1)
void k_u(const float* __restrict__ ctx, const float* __restrict__ gq,
         const float* __restrict__ bq, const float* __restrict__ Vl,
         const float* __restrict__ gl) {
    extern __shared__ char sm[];
    __nv_bfloat16* A    = (__nv_bfloat16*)sm;               // 64 x 520 (66560 B)
    __nv_bfloat16* W    = (__nv_bfloat16*)(sm + 66560);     // 64 x 520 (66560 B)
    float*         bq_s = (float*)(sm + 133120);            // 512 f32
    float*         wl_s = (float*)(sm + 135168);            // 512 f32

    const int tid = threadIdx.x;
    const int l   = blockIdx.x;
    const int hbase = blockIdx.y * 128;
    const float s_q = gq[0] * rsqrtf(g_sumsq[1]);
    const float s_l = gl[0] * rsqrtf(g_sumsq[2]);

    for (int i = tid; i < Hdim; i += 256) { bq_s[i] = bq[i]; wl_s[i] = s_l * Vl[i]; }

    // prefetch W chunk 0 (64 h rows x 512 k) via cp.async
    {
        const __nv_bfloat16* src = g_Wq + (size_t)hbase * DQ;
        #pragma unroll
        for (int it = 0; it < 16; ++it) {
            int i = tid + it * 256; int r = i >> 6, c8 = i & 63;
            CPA16(sptr(W + r * SU + c8 * 8), src + (size_t)r * DQ + c8 * 8);
        }
        CPCOMMIT();
    }

    // stage ctx rows b=0..63 (strided in gmem), convert to bf16
    #pragma unroll 4
    for (int it = 0; it < 32; ++it) {
        int i  = tid + it * 256;          // 8192 float4
        int r  = i >> 7, c4 = i & 127;
        float4 f = *(const float4*)(ctx + ((size_t)r * Ldim + l) * DQ + c4 * 4);
        __nv_bfloat16* ap = A + r * SU + c4 * 4;
        *(__nv_bfloat162*)(ap)     = __floats2bfloat162_rn(f.x, f.y);
        *(__nv_bfloat162*)(ap + 2) = __floats2bfloat162_rn(f.z, f.w);
    }

    const int lane = tid & 31, warp = tid >> 5;
    const int wm = warp & 1, wn = warp >> 1;      // 2 warps M(64), 4 warps N(64)
    const int grp = lane >> 2, lane4 = lane & 3;

    const int aRowL = (lane & 7) + ((lane >> 3) & 1) * 8;
    const int aColL = (lane >> 4) * 8;
    unsigned aAddr[2];
    #pragma unroll
    for (int mf = 0; mf < 2; ++mf)
        aAddr[mf] = sptr(A + (wm*32 + mf*16 + aRowL) * SU + aColL);
    const int bRowL = wn*16 + (lane & 7) + (lane >> 4) * 8;
    const int bColL = ((lane >> 3) & 1) * 8;
    const unsigned bAddr = sptr(W + bRowL * SU + bColL);

    for (int c = 0; c < 2; ++c) {
        CPWAIT0();
        __syncthreads();

        float acc[2][2][4] = {};
        #pragma unroll
        for (int ks = 0; ks < 32; ++ks) {
            unsigned a[2][4], b[4];
            ldsm4(a[0], aAddr[0] + ks*32);
            ldsm4(a[1], aAddr[1] + ks*32);
            ldsm4(b, bAddr + ks*32);
            #pragma unroll
            for (int mf = 0; mf < 2; ++mf) {
                mma_bf16(acc[mf][0], a[mf], b);
                mma_bf16(acc[mf][1], a[mf], b + 2);
            }
        }
        __syncthreads();   // all warps done reading W before refill

        if (c == 0) {      // prefetch chunk 1; overlaps epilogue stores below
            const __nv_bfloat16* src = g_Wq + (size_t)(hbase + 64) * DQ;
            #pragma unroll
            for (int it = 0; it < 16; ++it) {
                int i = tid + it * 256; int r = i >> 6, c8 = i & 63;
                CPA16(sptr(W + r * SU + c8 * 8), src + (size_t)r * DQ + c8 * 8);
            }
            CPCOMMIT();
        }

        // epilogue: u = relu(s_q*c + bq)*wl  -> gmem
        const int h0 = hbase + c*64 + wn*16 + lane4*2;
        #pragma unroll
        for (int mf = 0; mf < 2; ++mf) {
            int r0 = wm*32 + mf*16 + grp, r1 = r0 + 8;
            #pragma unroll
            for (int nf = 0; nf < 2; ++nf) {
                int h = h0 + nf*8;
                float2 o0, o1;
                o0.x = fmaxf(fmaf(s_q, acc[mf][nf][0], bq_s[h]),   0.f) * wl_s[h];
                o0.y = fmaxf(fmaf(s_q, acc[mf][nf][1], bq_s[h+1]), 0.f) * wl_s[h+1];
                o1.x = fmaxf(fmaf(s_q, acc[mf][nf][2], bq_s[h]),   0.f) * wl_s[h];
                o1.y = fmaxf(fmaf(s_q, acc[mf][nf][3], bq_s[h+1]), 0.f) * wl_s[h+1];
                *(float2*)&g_u[(size_t)(l*64 + r0) * Hdim + h] = o0;
                *(float2*)&g_u[(size_t)(l*64 + r1) * Hdim + h] = o1;
            }
        }
    }
}

// ---------------------------------------------------------------------------
// k_main: 4 (l,b) pairs per block. Fused v-proj GEMM (ldmatrix + mma, double-
// buffered W via cp.async) -> logits -> softmax -> fp32 weighted sum of v.
#define SA   264   // bf16 row stride (256 + 8 pad); 528 B, 16B aligned
#define LBPB 4
#define MROW 144   // real rows (4 * 36)
#define MPAD 160   // padded to 10 m16 tiles
__global__ __launch_bounds__(256, 1)
void k_main(const float* __restrict__ v, const int* __restrict__ lengths,
            const float* __restrict__ gv, const float* __restrict__ bv,
            float* __restrict__ out) {
    extern __shared__ char sm[];
    __nv_bfloat16* A    = (__nv_bfloat16*)sm;              // 160 x 264 (84480 B)
    __nv_bfloat16* W    = (__nv_bfloat16*)(sm + 84480);    // 2 bufs x 64 x 264 (67584 B)
    float*         u_s  = (float*)(sm + 152064);           // 4 x 512 f32 (8192 B)
    float*         bv_s = (float*)(sm + 160256);           // 512 f32
    float*         lg   = (float*)(sm + 162304);           // 160 f32
    int*           len_s= (int*)(sm + 162944);             // 4

    const int tid = threadIdx.x;
    const int lb0 = blockIdx.x * LBPB;
    const float s_v = gv[0] * rsqrtf(g_sumsq[0]);

    // phase 0: stage u + bv, zero logits + A pad rows
    #pragma unroll
    for (int it = 0; it < 2; ++it) {
        int i = tid + it * 256;   // 512 float4 = 2048 f32
        ((float4*)u_s)[i] = ((const float4*)(g_u + (size_t)lb0 * Hdim))[i];
    }
    if (tid < 128) ((float4*)bv_s)[tid] = ((const float4*)bv)[tid];
    if (tid < MPAD) lg[tid] = 0.f;
    for (int i = tid; i < (MPAD - MROW) * SA / 2; i += 256)   // 16 rows x 264 bf16
        ((unsigned*)(A + MROW * SA))[i] = 0u;

    // prefetch W chunk 0
    {
        #pragma unroll
        for (int it = 0; it < 8; ++it) {
            int i = tid + it * 256; int r = i >> 5, c8 = i & 31;
            CPA16(sptr(W + r * SA + c8 * 8), g_Wv + (size_t)r * DV + c8 * 8);
        }
        CPCOMMIT();
    }

    // phase 1: v (144 contiguous rows) -> bf16 A
    const float* vsrc = v + (size_t)lb0 * KDET * DV;
    #pragma unroll 4
    for (int it = 0; it < 36; ++it) {
        int i = tid + it * 256;           // 9216 float4
        int r = i >> 6, c4 = i & 63;
        float4 f = *(const float4*)(vsrc + (size_t)i * 4);
        __nv_bfloat16* ap = A + r * SA + c4 * 4;
        *(__nv_bfloat162*)(ap)     = __floats2bfloat162_rn(f.x, f.y);
        *(__nv_bfloat162*)(ap + 2) = __floats2bfloat162_rn(f.z, f.w);
    }

    const int lane = tid & 31, warp = tid >> 5;
    const int wm = warp & 1, wn = warp >> 1;      // 2 warps M(160), 4 warps N(64)
    const int grp = lane >> 2, lane4 = lane & 3;

    const int aRowL = (lane & 7) + ((lane >> 3) & 1) * 8;
    const int aColL = (lane >> 4) * 8;
    unsigned aAddr[5];
    #pragma unroll
    for (int mf = 0; mf < 5; ++mf)
        aAddr[mf] = sptr(A + (wm*80 + mf*16 + aRowL) * SA + aColL);
    const int bRowL = wn*16 + (lane & 7) + (lane >> 4) * 8;
    const int bColL = ((lane >> 3) & 1) * 8;
    unsigned bAddrBase[2];
    bAddrBase[0] = sptr(W + bRowL * SA + bColL);
    bAddrBase[1] = sptr(W + 64*SA + bRowL * SA + bColL);

    // row -> lb mapping, validity
    int r0v[5], r1v[5], u0i[5], u1i[5];
    bool ok0[5], ok1[5];
    #pragma unroll
    for (int mf = 0; mf < 5; ++mf) {
        int r0 = wm*80 + mf*16 + grp, r1 = r0 + 8;
        r0v[mf] = r0; r1v[mf] = r1;
        ok0[mf] = r0 < MROW; ok1[mf] = r1 < MROW;
        u0i[mf] = (ok0[mf] ? (r0 / KDET) : 0) * Hdim;
        u1i[mf] = (ok1[mf] ? (r1 / KDET) : 0) * Hdim;
    }
    float part0[5] = {0,0,0,0,0}, part1[5] = {0,0,0,0,0};

    for (int c = 0; c < 8; ++c) {
        if (c < 7) {
            const __nv_bfloat16* src = g_Wv + (size_t)(c+1) * 64 * DV;
            __nv_bfloat16* dst = W + ((c+1) & 1) * 64 * SA;
            #pragma unroll
            for (int it = 0; it < 8; ++it) {
                int i = tid + it * 256; int r = i >> 5, c8 = i & 31;
                CPA16(sptr(dst + r * SA + c8 * 8), src + (size_t)r * DV + c8 * 8);
            }
            CPCOMMIT();
            CPWAIT1();
        } else {
            CPWAIT0();
        }
        __syncthreads();

        float acc[5][2][4] = {};
        const unsigned bB = bAddrBase[c & 1];
        #pragma unroll
        for (int ks = 0; ks < 16; ++ks) {
            unsigned a[5][4], b[4];
            #pragma unroll
            for (int mf = 0; mf < 5; ++mf) ldsm4(a[mf], aAddr[mf] + ks*32);
            ldsm4(b, bB + ks*32);
            #pragma unroll
            for (int mf = 0; mf < 5; ++mf) {
                mma_bf16(acc[mf][0], a[mf], b);
                mma_bf16(acc[mf][1], a[mf], b + 2);
            }
        }

        // epilogue partial: relu-dot with u, accumulate in registers
        const int hb = c*64 + wn*16 + lane4*2;
        #pragma unroll
        for (int mf = 0; mf < 5; ++mf) {
            float slo = 0.f, shi = 0.f;
            #pragma unroll
            for (int nf = 0; nf < 2; ++nf) {
                int h = hb + nf*8;
                float b0 = bv_s[h], b1 = bv_s[h+1];
                slo += fmaxf(fmaf(s_v, acc[mf][nf][0], b0), 0.f) * u_s[u0i[mf] + h]
                     + fmaxf(fmaf(s_v, acc[mf][nf][1], b1), 0.f) * u_s[u0i[mf] + h + 1];
                shi += fmaxf(fmaf(s_v, acc[mf][nf][2], b0), 0.f) * u_s[u1i[mf] + h]
                     + fmaxf(fmaf(s_v, acc[mf][nf][3], b1), 0.f) * u_s[u1i[mf] + h + 1];
            }
            part0[mf] += slo; part1[mf] += shi;
        }
        __syncthreads();
    }

    // final reduce over lane%4 quad -> logits
    #pragma unroll
    for (int mf = 0; mf < 5; ++mf) {
        float slo = part0[mf], shi = part1[mf];
        slo += __shfl_xor_sync(~0u, slo, 1); slo += __shfl_xor_sync(~0u, slo, 2);
        shi += __shfl_xor_sync(~0u, shi, 1); shi += __shfl_xor_sync(~0u, shi, 2);
        if (lane4 == 0) {
            if (ok0[mf]) atomicAdd(&lg[r0v[mf]], slo);
            if (ok1[mf]) atomicAdd(&lg[r1v[mf]], shi);
        }
    }
    __syncthreads();

    // softmax over valid k (serial per lb — 36 entries)
    if (tid < LBPB) {
        int len = lengths[lb0 + tid];
        if (len > KDET) len = KDET;
        len_s[tid] = len;
        float* Lg = lg + tid * KDET;
        if (len > 0) {
            float m = -1e30f;
            for (int k = 0; k < len; ++k) m = fmaxf(m, Lg[k]);
            float s = 0.f;
            for (int k = 0; k < len; ++k) { float e = __expf(Lg[k] - m); Lg[k] = e; s += e; }
            float inv = 1.f / s;
            for (int k = 0; k < len; ++k) Lg[k] *= inv;
        }
    }
    __syncthreads();

    // fp32 weighted sum of v (re-read from gmem; L2-hot), write out [B, L, Dv]
    const int lbi = tid >> 6, t = tid & 63;
    const int len = len_s[lbi];
    const float* vr = v + ((size_t)(lb0 + lbi) * KDET) * DV + t*4;
    const float* Lg = lg + lbi * KDET;
    float4 o; o.x = 0.f; o.y = 0.f; o.z = 0.f; o.w = 0.f;
    for (int k = 0; k < len; ++k) {
        float w = Lg[k];
        float4 x = *(const float4*)(vr + (size_t)k * DV);
        o.x = fmaf(w, x.x, o.x); o.y = fmaf(w, x.y, o.y);
        o.z = fmaf(w, x.z, o.z); o.w = fmaf(w, x.w, o.w);
    }
    const int lb = lb0 + lbi, l = lb >> 6, bb = lb & 63;
    *(float4*)(out + ((size_t)bb * Ldim + l) * DV + t*4) = o;
}

// ---------------------------------------------------------------------------
extern "C" void kernel_launch(void* const* d_in, const int* in_sizes, int n_in,
                              void* d_out, int out_size) {
    const float* ctx     = (const float*)d_in[0];
    const float* v       = (const float*)d_in[1];
    const int*   lengths = (const int*)  d_in[2];
    const float* Vv      = (const float*)d_in[3];
    const float* gv      = (const float*)d_in[4];
    const float* bvp     = (const float*)d_in[5];
    const float* Vq      = (const float*)d_in[6];
    const float* gq      = (const float*)d_in[7];
    const float* bq      = (const float*)d_in[8];
    const float* Vl      = (const float*)d_in[9];
    const float* gl      = (const float*)d_in[10];
    // d_in[11] = bl: constant logit shift, cancels in softmax.
    (void)in_sizes; (void)n_in; (void)out_size;

    cudaFuncSetAttribute(k_u,    cudaFuncAttributeMaxDynamicSharedMemorySize, 137216);
    cudaFuncSetAttribute(k_main, cudaFuncAttributeMaxDynamicSharedMemorySize, 162960);

    k_zero<<<1, 32>>>();
    k_sumsq<<<128, 256>>>(Vv, Vq, Vl);
    k_convert<<<(Hdim*DQ + 255) / 256, 256>>>(Vv, Vq);
    dim3 gu(Ldim, 4);
    k_u<<<gu, 256, 137216>>>(ctx, gq, bq, Vl, gl);
    k_main<<<NLB / LBPB, 256, 162960>>>(v, lengths, gv, bvp, (float*)d_out);
}

// round 7
// speedup vs baseline: 2.0446x; 1.1447x over previous
#include <cuda_runtime.h>
#include <cuda_bf16.h>
#include <math.h>
#include <stdint.h>

// Problem constants
#define Bdim 64
#define Ldim 80
#define KDET 36
#define DV   256
#define DQ   512
#define Hdim 512
#define NLB  (Ldim*Bdim)   // 5120

// Scratch (__device__ globals: no runtime allocation allowed)
__device__ float          g_sumsq[3];
__device__ __nv_bfloat16  g_Wv[Hdim*DV];
__device__ __nv_bfloat16  g_Wq[Hdim*DQ];
__device__ float          g_u[(size_t)NLB*Hdim];

// ---------------------------------------------------------------------------
__device__ __forceinline__ unsigned sptr(const void* p) {
    return (unsigned)__cvta_generic_to_shared(p);
}
__device__ __forceinline__ void ldsm4(unsigned* r, unsigned a) {
    asm volatile("ldmatrix.sync.aligned.m8n8.x4.shared.b16 {%0,%1,%2,%3}, [%4];\n"
                 : "=r"(r[0]), "=r"(r[1]), "=r"(r[2]), "=r"(r[3]) : "r"(a));
}
#define CPA16(dst, src) asm volatile("cp.async.cg.shared.global [%0], [%1], 16;\n" :: "r"(dst), "l"(src))
#define CPCOMMIT()      asm volatile("cp.async.commit_group;\n")
#define CPWAIT1()       asm volatile("cp.async.wait_group 1;\n")
#define CPWAIT0()       asm volatile("cp.async.wait_group 0;\n")

__device__ __forceinline__ void mma_bf16(float* c, const unsigned* a, const unsigned* b) {
    asm volatile(
        "mma.sync.aligned.m16n8k16.row.col.f32.bf16.bf16.f32 "
        "{%0,%1,%2,%3}, {%4,%5,%6,%7}, {%8,%9}, {%0,%1,%2,%3};\n"
        : "+f"(c[0]), "+f"(c[1]), "+f"(c[2]), "+f"(c[3])
        : "r"(a[0]), "r"(a[1]), "r"(a[2]), "r"(a[3]), "r"(b[0]), "r"(b[1]));
}

// ---------------------------------------------------------------------------
__global__ void k_zero() { if (threadIdx.x < 3) g_sumsq[threadIdx.x] = 0.f; }

__global__ void k_sumsq(const float* __restrict__ Vv, const float* __restrict__ Vq,
                        const float* __restrict__ Vl) {
    float sv = 0.f, sq = 0.f, sl = 0.f;
    int stride = gridDim.x * blockDim.x;
    for (int i = blockIdx.x * blockDim.x + threadIdx.x; i < Hdim*DQ; i += stride) {
        float x = Vq[i]; sq += x*x;
        if (i < Hdim*DV) { float y = Vv[i]; sv += y*y; }
        if (i < Hdim)    { float z = Vl[i]; sl += z*z; }
    }
    #pragma unroll
    for (int o = 16; o; o >>= 1) {
        sv += __shfl_xor_sync(~0u, sv, o);
        sq += __shfl_xor_sync(~0u, sq, o);
        sl += __shfl_xor_sync(~0u, sl, o);
    }
    __shared__ float rs[3][8];
    int w = threadIdx.x >> 5;
    if ((threadIdx.x & 31) == 0) { rs[0][w] = sv; rs[1][w] = sq; rs[2][w] = sl; }
    __syncthreads();
    if (threadIdx.x == 0) {
        float a = 0.f, b = 0.f, c = 0.f;
        for (int i = 0; i < 8; ++i) { a += rs[0][i]; b += rs[1][i]; c += rs[2][i]; }
        atomicAdd(&g_sumsq[0], a); atomicAdd(&g_sumsq[1], b); atomicAdd(&g_sumsq[2], c);
    }
}

__global__ void k_convert(const float* __restrict__ Vv, const float* __restrict__ Vq) {
    int i = blockIdx.x * blockDim.x + threadIdx.x;
    if (i < Hdim*DQ) g_Wq[i] = __float2bfloat16(Vq[i]);
    if (i < Hdim*DV) g_Wv[i] = __float2bfloat16(Vv[i]);
}

// ---------------------------------------------------------------------------
// k_u: u[lb][h] = relu(s_q*(ctx.Vq_h)+bq_h)*s_l*Vl_h
// grid (80 l, 8 h-slices of 64). GEMM [64 x 512] x [512 x 64]^T per block,
// single W chunk, pipelined ldmatrix->mma mainloop.
#define SU 520   // bf16 row stride (512 + 8 pad); ldsm conflict-free
__global__ __launch_bounds__(256, 1)
void k_u(const float* __restrict__ ctx, const float* __restrict__ gq,
         const float* __restrict__ bq, const float* __restrict__ Vl,
         const float* __restrict__ gl) {
    extern __shared__ __align__(16) char sm[];
    __nv_bfloat16* A    = (__nv_bfloat16*)sm;               // 64 x 520 (66560 B)
    __nv_bfloat16* W    = (__nv_bfloat16*)(sm + 66560);     // 64 x 520 (66560 B)
    float*         bq_s = (float*)(sm + 133120);            // 512 f32
    float*         wl_s = (float*)(sm + 135168);            // 512 f32

    const int tid = threadIdx.x;
    const int l   = blockIdx.x;
    const int hbase = blockIdx.y * 64;
    const float s_q = gq[0] * rsqrtf(g_sumsq[1]);
    const float s_l = gl[0] * rsqrtf(g_sumsq[2]);

    for (int i = tid; i < Hdim; i += 256) { bq_s[i] = bq[i]; wl_s[i] = s_l * Vl[i]; }

    // W (64 h-rows x 512 k) via cp.async
    {
        const __nv_bfloat16* src = g_Wq + (size_t)hbase * DQ;
        #pragma unroll
        for (int it = 0; it < 16; ++it) {
            int i = tid + it * 256; int r = i >> 6, c8 = i & 63;
            CPA16(sptr(W + r * SU + c8 * 8), src + (size_t)r * DQ + c8 * 8);
        }
        CPCOMMIT();
    }

    // stage ctx rows b=0..63 (strided in gmem), convert to bf16
    #pragma unroll 4
    for (int it = 0; it < 32; ++it) {
        int i  = tid + it * 256;
        int r  = i >> 7, c4 = i & 127;
        float4 f = *(const float4*)(ctx + ((size_t)r * Ldim + l) * DQ + c4 * 4);
        __nv_bfloat16* ap = A + r * SU + c4 * 4;
        *(__nv_bfloat162*)(ap)     = __floats2bfloat162_rn(f.x, f.y);
        *(__nv_bfloat162*)(ap + 2) = __floats2bfloat162_rn(f.z, f.w);
    }

    const int lane = tid & 31, warp = tid >> 5;
    const int wm = warp & 1, wn = warp >> 1;      // 2 warps M(64), 4 warps N(64)
    const int grp = lane >> 2, lane4 = lane & 3;

    const int aRowL = (lane & 7) + ((lane >> 3) & 1) * 8;
    const int aColL = (lane >> 4) * 8;
    unsigned aAddr[2];
    #pragma unroll
    for (int mf = 0; mf < 2; ++mf)
        aAddr[mf] = sptr(A + (wm*32 + mf*16 + aRowL) * SU + aColL);
    const int bRowL = wn*16 + (lane & 7) + (lane >> 4) * 8;
    const int bColL = ((lane >> 3) & 1) * 8;
    const unsigned bAddr = sptr(W + bRowL * SU + bColL);

    CPWAIT0();
    __syncthreads();

    // pipelined mainloop over K=512 (32 k16 steps)
    float acc[2][2][4] = {};
    unsigned aF[2][2][4], bF[2][4];
    ldsm4(aF[0][0], aAddr[0]);
    ldsm4(aF[0][1], aAddr[1]);
    ldsm4(bF[0], bAddr);
    #pragma unroll
    for (int ks = 0; ks < 32; ++ks) {
        const int cur = ks & 1, nxt = cur ^ 1;
        if (ks < 31) {
            const unsigned off = (unsigned)(ks + 1) * 32;
            ldsm4(aF[nxt][0], aAddr[0] + off);
            ldsm4(aF[nxt][1], aAddr[1] + off);
            ldsm4(bF[nxt], bAddr + off);
        }
        #pragma unroll
        for (int mf = 0; mf < 2; ++mf) {
            mma_bf16(acc[mf][0], aF[cur][mf], bF[cur]);
            mma_bf16(acc[mf][1], aF[cur][mf], bF[cur] + 2);
        }
    }

    // epilogue: u = relu(s_q*c + bq)*wl  -> gmem
    const int h0 = hbase + wn*16 + lane4*2;
    #pragma unroll
    for (int mf = 0; mf < 2; ++mf) {
        int r0 = wm*32 + mf*16 + grp, r1 = r0 + 8;
        #pragma unroll
        for (int nf = 0; nf < 2; ++nf) {
            int h = h0 + nf*8;
            float2 o0, o1;
            o0.x = fmaxf(fmaf(s_q, acc[mf][nf][0], bq_s[h]),   0.f) * wl_s[h];
            o0.y = fmaxf(fmaf(s_q, acc[mf][nf][1], bq_s[h+1]), 0.f) * wl_s[h+1];
            o1.x = fmaxf(fmaf(s_q, acc[mf][nf][2], bq_s[h]),   0.f) * wl_s[h];
            o1.y = fmaxf(fmaf(s_q, acc[mf][nf][3], bq_s[h+1]), 0.f) * wl_s[h+1];
            *(float2*)&g_u[(size_t)(l*64 + r0) * Hdim + h] = o0;
            *(float2*)&g_u[(size_t)(l*64 + r1) * Hdim + h] = o1;
        }
    }
}

// ---------------------------------------------------------------------------
// k_main: 5 (l,b) pairs per block (M=192 pad, 180 real). Warp layout 4x2,
// pipelined ldmatrix->mma, double-buffered W via cp.async; fused epilogue:
// relu-dot vs u -> logits -> softmax -> fp32 weighted sum of v.
#define SA   264   // bf16 row stride (256 + 8 pad)
#define LBPB 5
#define MROW 180   // real rows (5 * 36)
#define MPAD 192   // 12 m16 tiles
// smem offsets
#define KM_A   0
#define KM_W   101376      // A: 192*264*2
#define KM_U   168960      // W: 2*64*264*2 = 67584
#define KM_BV  179200      // u_s: 5*512*4 = 10240
#define KM_LG  181248      // bv: 2048
#define KM_LEN 182016      // lg: 192*4
#define KM_SMEM 182048
__global__ __launch_bounds__(256, 1)
void k_main(const float* __restrict__ v, const int* __restrict__ lengths,
            const float* __restrict__ gv, const float* __restrict__ bv,
            float* __restrict__ out) {
    extern __shared__ __align__(16) char sm[];
    __nv_bfloat16* A    = (__nv_bfloat16*)(sm + KM_A);
    __nv_bfloat16* W    = (__nv_bfloat16*)(sm + KM_W);
    float*         u_s  = (float*)(sm + KM_U);
    float*         bv_s = (float*)(sm + KM_BV);
    float*         lg   = (float*)(sm + KM_LG);
    int*           len_s= (int*)(sm + KM_LEN);

    const int tid = threadIdx.x;
    const int lb0 = blockIdx.x * LBPB;
    const float s_v = gv[0] * rsqrtf(g_sumsq[0]);

    // phase 0: stage u + bv, zero logits + A pad rows
    for (int i = tid; i < LBPB * 128; i += 256)   // 640 float4 = 2560 f32
        ((float4*)u_s)[i] = ((const float4*)(g_u + (size_t)lb0 * Hdim))[i];
    if (tid < 128) ((float4*)bv_s)[tid] = ((const float4*)bv)[tid];
    if (tid < MPAD) lg[tid] = 0.f;
    for (int i = tid; i < (MPAD - MROW) * SA / 2; i += 256)   // 12 rows x 264 bf16
        ((unsigned*)(A + MROW * SA))[i] = 0u;

    // prefetch W chunk 0
    {
        #pragma unroll
        for (int it = 0; it < 8; ++it) {
            int i = tid + it * 256; int r = i >> 5, c8 = i & 31;
            CPA16(sptr(W + r * SA + c8 * 8), g_Wv + (size_t)r * DV + c8 * 8);
        }
        CPCOMMIT();
    }

    // phase 1: v (180 contiguous rows x 256 f32) -> bf16 A
    const float* vsrc = v + (size_t)lb0 * KDET * DV;
    #pragma unroll 5
    for (int it = 0; it < 45; ++it) {
        int i = tid + it * 256;           // 11520 float4
        int r = i >> 6, c4 = i & 63;
        float4 f = *(const float4*)(vsrc + (size_t)i * 4);
        __nv_bfloat16* ap = A + r * SA + c4 * 4;
        *(__nv_bfloat162*)(ap)     = __floats2bfloat162_rn(f.x, f.y);
        *(__nv_bfloat162*)(ap + 2) = __floats2bfloat162_rn(f.z, f.w);
    }

    const int lane = tid & 31, warp = tid >> 5;
    const int wm = warp & 3, wn = warp >> 2;      // 4 warps over M(192), 2 over N(64)
    const int grp = lane >> 2, lane4 = lane & 3;

    const int aRowL = (lane & 7) + ((lane >> 3) & 1) * 8;
    const int aColL = (lane >> 4) * 8;
    unsigned aAddr[3];
    #pragma unroll
    for (int mf = 0; mf < 3; ++mf)
        aAddr[mf] = sptr(A + (wm*48 + mf*16 + aRowL) * SA + aColL);
    const int bRowL = wn*32 + (lane & 7) + (lane >> 4) * 8;
    const int bColL = ((lane >> 3) & 1) * 8;
    unsigned bAddrBase[2];
    bAddrBase[0] = sptr(W + bRowL * SA + bColL);
    bAddrBase[1] = sptr(W + 64*SA + bRowL * SA + bColL);
    const unsigned bOff16 = 16 * SA * 2;          // +16 B-rows

    // row -> lb mapping, validity
    int r0v[3], r1v[3], u0i[3], u1i[3];
    bool ok0[3], ok1[3];
    #pragma unroll
    for (int mf = 0; mf < 3; ++mf) {
        int r0 = wm*48 + mf*16 + grp, r1 = r0 + 8;
        r0v[mf] = r0; r1v[mf] = r1;
        ok0[mf] = r0 < MROW; ok1[mf] = r1 < MROW;
        u0i[mf] = (ok0[mf] ? (r0 / KDET) : 0) * Hdim;
        u1i[mf] = (ok1[mf] ? (r1 / KDET) : 0) * Hdim;
    }
    float part0[3] = {0,0,0}, part1[3] = {0,0,0};

    for (int c = 0; c < 8; ++c) {
        if (c < 7) {
            const __nv_bfloat16* src = g_Wv + (size_t)(c+1) * 64 * DV;
            __nv_bfloat16* dst = W + ((c+1) & 1) * 64 * SA;
            #pragma unroll
            for (int it = 0; it < 8; ++it) {
                int i = tid + it * 256; int r = i >> 5, c8 = i & 31;
                CPA16(sptr(dst + r * SA + c8 * 8), src + (size_t)r * DV + c8 * 8);
            }
            CPCOMMIT();
            CPWAIT1();
        } else {
            CPWAIT0();
        }
        __syncthreads();

        // pipelined mainloop over K=256 (16 k16 steps)
        float acc[3][4][4] = {};
        const unsigned bB = bAddrBase[c & 1];
        unsigned aF[2][3][4], bF[2][8];
        ldsm4(aF[0][0], aAddr[0]);
        ldsm4(aF[0][1], aAddr[1]);
        ldsm4(aF[0][2], aAddr[2]);
        ldsm4(bF[0],     bB);
        ldsm4(bF[0] + 4, bB + bOff16);
        #pragma unroll
        for (int ks = 0; ks < 16; ++ks) {
            const int cur = ks & 1, nxt = cur ^ 1;
            if (ks < 15) {
                const unsigned off = (unsigned)(ks + 1) * 32;
                ldsm4(aF[nxt][0], aAddr[0] + off);
                ldsm4(aF[nxt][1], aAddr[1] + off);
                ldsm4(aF[nxt][2], aAddr[2] + off);
                ldsm4(bF[nxt],     bB + off);
                ldsm4(bF[nxt] + 4, bB + bOff16 + off);
            }
            #pragma unroll
            for (int mf = 0; mf < 3; ++mf)
                #pragma unroll
                for (int nf = 0; nf < 4; ++nf)
                    mma_bf16(acc[mf][nf], aF[cur][mf], bF[cur] + nf*2);
        }

        // epilogue partial: relu-dot with u, accumulate in registers
        const int hb = c*64 + wn*32 + lane4*2;
        #pragma unroll
        for (int mf = 0; mf < 3; ++mf) {
            float slo = 0.f, shi = 0.f;
            #pragma unroll
            for (int nf = 0; nf < 4; ++nf) {
                int h = hb + nf*8;
                float b0 = bv_s[h], b1 = bv_s[h+1];
                slo += fmaxf(fmaf(s_v, acc[mf][nf][0], b0), 0.f) * u_s[u0i[mf] + h]
                     + fmaxf(fmaf(s_v, acc[mf][nf][1], b1), 0.f) * u_s[u0i[mf] + h + 1];
                shi += fmaxf(fmaf(s_v, acc[mf][nf][2], b0), 0.f) * u_s[u1i[mf] + h]
                     + fmaxf(fmaf(s_v, acc[mf][nf][3], b1), 0.f) * u_s[u1i[mf] + h + 1];
            }
            part0[mf] += slo; part1[mf] += shi;
        }
        __syncthreads();
    }

    // final reduce over lane%4 quad -> logits
    #pragma unroll
    for (int mf = 0; mf < 3; ++mf) {
        float slo = part0[mf], shi = part1[mf];
        slo += __shfl_xor_sync(~0u, slo, 1); slo += __shfl_xor_sync(~0u, slo, 2);
        shi += __shfl_xor_sync(~0u, shi, 1); shi += __shfl_xor_sync(~0u, shi, 2);
        if (lane4 == 0) {
            if (ok0[mf]) atomicAdd(&lg[r0v[mf]], slo);
            if (ok1[mf]) atomicAdd(&lg[r1v[mf]], shi);
        }
    }
    __syncthreads();

    // softmax over valid k (serial per lb — 36 entries)
    if (tid < LBPB) {
        int len = lengths[lb0 + tid];
        if (len > KDET) len = KDET;
        if (len < 0) len = 0;
        len_s[tid] = len;
        float* Lg = lg + tid * KDET;
        if (len > 0) {
            float m = -1e30f;
            for (int k = 0; k < len; ++k) m = fmaxf(m, Lg[k]);
            float s = 0.f;
            for (int k = 0; k < len; ++k) { float e = __expf(Lg[k] - m); Lg[k] = e; s += e; }
            float inv = 1.f / s;
            for (int k = 0; k < len; ++k) Lg[k] *= inv;
        }
    }
    __syncthreads();

    // fp32 weighted sum of v (re-read from gmem; L2-hot), write out [B, L, Dv]
    for (int i = tid; i < LBPB * 64; i += 256) {
        const int lbi = i >> 6, t = i & 63;
        const int len = len_s[lbi];
        const float* vr = v + ((size_t)(lb0 + lbi) * KDET) * DV + t*4;
        const float* Lg = lg + lbi * KDET;
        float4 o; o.x = 0.f; o.y = 0.f; o.z = 0.f; o.w = 0.f;
        for (int k = 0; k < len; ++k) {
            float w = Lg[k];
            float4 x = *(const float4*)(vr + (size_t)k * DV);
            o.x = fmaf(w, x.x, o.x); o.y = fmaf(w, x.y, o.y);
            o.z = fmaf(w, x.z, o.z); o.w = fmaf(w, x.w, o.w);
        }
        const int lb = lb0 + lbi, l = lb >> 6, bb = lb & 63;
        *(float4*)(out + ((size_t)bb * Ldim + l) * DV + t*4) = o;
    }
}

// ---------------------------------------------------------------------------
extern "C" void kernel_launch(void* const* d_in, const int* in_sizes, int n_in,
                              void* d_out, int out_size) {
    const float* ctx     = (const float*)d_in[0];
    const float* v       = (const float*)d_in[1];
    const int*   lengths = (const int*)  d_in[2];
    const float* Vv      = (const float*)d_in[3];
    const float* gv      = (const float*)d_in[4];
    const float* bvp     = (const float*)d_in[5];
    const float* Vq      = (const float*)d_in[6];
    const float* gq      = (const float*)d_in[7];
    const float* bq      = (const float*)d_in[8];
    const float* Vl      = (const float*)d_in[9];
    const float* gl      = (const float*)d_in[10];
    // d_in[11] = bl: constant logit shift, cancels in softmax.
    (void)in_sizes; (void)n_in; (void)out_size;

    cudaFuncSetAttribute(k_u,    cudaFuncAttributeMaxDynamicSharedMemorySize, 137216);
    cudaFuncSetAttribute(k_main, cudaFuncAttributeMaxDynamicSharedMemorySize, KM_SMEM);

    k_zero<<<1, 32>>>();
    k_sumsq<<<128, 256>>>(Vv, Vq, Vl);
    k_convert<<<(Hdim*DQ + 255) / 256, 256>>>(Vv, Vq);
    dim3 gu(Ldim, 8);
    k_u<<<gu, 256, 137216>>>(ctx, gq, bq, Vl, gl);
    k_main<<<NLB / LBPB, 256, KM_SMEM>>>(v, lengths, gv, bvp, (float*)d_out);
}